// round 16
// baseline (speedup 1.0000x reference)
#include <cuda_runtime.h>
#include <cuda_bf16.h>
#include <math.h>
#include <stdint.h>

typedef uint32_t u32;
typedef uint64_t u64;

#define T_LEN 262144
#define B_N 8
#define C_N 8
#define K_N 50
#define TILE_M 256

// Ping-pong hidden state [B][C][T]
__device__ float g_h0[B_N * C_N * T_LEN];
__device__ float g_h1[B_N * C_N * T_LEN];
// Layer-0 scalar weights [k][o]
__device__ float g_W0[K_N * C_N];
// Layers 1..17 int8 B fragments: [layer][group(13)][half(hi=0,lo=1)][lane(32)] uint2
__device__ uint2 g_Bq[17 * 13 * 64];
__device__ float g_wscale[17];
// |h| max bit-patterns; g_hmax_bits[i] = max |input of mma-layer i|
__device__ unsigned int g_hmax_bits[19];

// ---------------------------------------------------------------------------
__device__ __forceinline__ u32 smem_u32(const void* p) {
    return (u32)__cvta_generic_to_shared(p);
}
__device__ __forceinline__ void ldmA(u32& a0, u32& a1, u32& a2, u32& a3, u32 addr) {
    asm volatile("ldmatrix.sync.aligned.m8n8.x4.shared.b16 {%0,%1,%2,%3}, [%4];"
                 : "=r"(a0), "=r"(a1), "=r"(a2), "=r"(a3) : "r"(addr));
}
__device__ __forceinline__ void mma_s8(int* c, u32 a0, u32 a1, u32 a2, u32 a3,
                                       u32 b0, u32 b1) {
    asm volatile("mma.sync.aligned.m16n8k32.row.col.s32.s8.s8.s32 "
                 "{%0,%1,%2,%3},{%4,%5,%6,%7},{%8,%9},{%0,%1,%2,%3};"
                 : "+r"(c[0]), "+r"(c[1]), "+r"(c[2]), "+r"(c[3])
                 : "r"(a0), "r"(a1), "r"(a2), "r"(a3), "r"(b0), "r"(b1));
}
__device__ __forceinline__ u32 pack4i(int a, int b, int c, int d) {
    return (u32)(a & 0xff) | ((u32)(b & 0xff) << 8) |
           ((u32)(c & 0xff) << 16) | ((u32)(d & 0xff) << 24);
}
// tanh(x)*sigmoid(g) with ONE fast division.
__device__ __forceinline__ float gated_act(float x, float g) {
    x = fminf(fmaxf(x, -20.0f), 20.0f);
    g = fminf(fmaxf(g, -20.0f), 20.0f);
    float e = __expf(-2.0f * x);
    float f = __expf(-g);
    return __fdividef(1.0f - e, (1.0f + e) * (1.0f + f));
}

// ---------------------------------------------------------------------------
// Weight prep.  l=0: scalar fp32.  l>=1: weight-norm, 15-bit hi/lo int8 quant,
// pack B frags for 4-tap dense groups.  Group g covers ages 4g..4g+3 (52 taps,
// ages 50/51 zero).  A k-byte: r=k>>3 -> time row rb+r -> age 4g+3-r.
// Frag mapping (validated R9): lane=o*4+T; breg0 byte i <-> k=4T+i;
// breg1 byte i <-> k=16+4T+i.  So breg0: r=T>>1, c=4(T&1)+i, age=4g+3-(T>>1);
// breg1: age=4g+1-(T>>1).
// ---------------------------------------------------------------------------
__global__ void prep_weights(const float* __restrict__ v0,
                             const float* __restrict__ g0,
                             const float* __restrict__ vs,
                             const float* __restrict__ gs) {
    int l = blockIdx.x;
    int tid = threadIdx.x;

    if (l == 0) {
        if (tid < C_N) {
            int o = tid;
            float s = 0.0f;
            for (int k = 0; k < K_N; k++) {
                float x = v0[o * K_N + k];
                s += x * x;
            }
            float scale = g0[o] * rsqrtf(s);
            for (int k = 0; k < K_N; k++)
                g_W0[k * C_N + o] = scale * v0[o * K_N + k];
        }
        return;
    }

    __shared__ float osc[C_N];
    __shared__ float w_s[C_N * C_N * K_N];
    __shared__ float wred[8];
    __shared__ float swmax;

    const float* v = vs + (size_t)(l - 1) * C_N * C_N * K_N;
    int o8 = tid >> 5;
    int lane = tid & 31;

    {
        float s = 0.0f;
        for (int i = lane; i < C_N * K_N; i += 32) {
            float x = v[o8 * C_N * K_N + i];
            s += x * x;
        }
        #pragma unroll
        for (int off = 16; off > 0; off >>= 1)
            s += __shfl_down_sync(0xffffffffu, s, off);
        if (lane == 0) osc[o8] = gs[(l - 1) * C_N + o8] * rsqrtf(s);
    }
    __syncthreads();

    float m = 0.0f;
    for (int i = tid; i < 3200; i += 256) {
        float w = v[i] * osc[i / (C_N * K_N)];
        w_s[i] = w;
        m = fmaxf(m, fabsf(w));
    }
    #pragma unroll
    for (int off = 16; off > 0; off >>= 1)
        m = fmaxf(m, __shfl_down_sync(0xffffffffu, m, off));
    if (lane == 0) wred[o8] = m;
    __syncthreads();
    if (tid == 0) {
        float wm = wred[0];
        #pragma unroll
        for (int i = 1; i < 8; i++) wm = fmaxf(wm, wred[i]);
        swmax = wm;
        g_wscale[l - 1] = wm / 16256.0f;
    }
    __syncthreads();

    if (tid < 64) {
        int half = tid >> 5;            // 0 = hi, 1 = lo
        int ln = tid & 31;
        int o = ln >> 2;
        int T = ln & 3;
        int c0 = 4 * (T & 1);
        int rT = T >> 1;
        float inv = 16256.0f / swmax;
        for (int g = 0; g < 13; g++) {
            int age0 = 4 * g + 3 - rT;  // breg0 tap
            int age1 = 4 * g + 1 - rT;  // breg1 tap
            int v0b[4], v1b[4];
            #pragma unroll
            for (int i = 0; i < 4; i++) {
                int c = c0 + i;
                int Wh0 = 0, Wl0 = 0, Wh1 = 0, Wl1 = 0;
                if (age0 <= 49) {
                    int Wq = __float2int_rn(w_s[o * 400 + c * 50 + (49 - age0)] * inv);
                    Wh0 = (Wq + 64) >> 7;
                    Wl0 = Wq - (Wh0 << 7);
                }
                {
                    int Wq = __float2int_rn(w_s[o * 400 + c * 50 + (49 - age1)] * inv);
                    Wh1 = (Wq + 64) >> 7;
                    Wl1 = Wq - (Wh1 << 7);
                }
                v0b[i] = half ? Wl0 : Wh0;
                v1b[i] = half ? Wl1 : Wh1;
            }
            g_Bq[(size_t)(l - 1) * 832 + g * 64 + half * 32 + ln] =
                make_uint2(pack4i(v0b[0], v0b[1], v0b[2], v0b[3]),
                           pack4i(v1b[0], v1b[1], v1b[2], v1b[3]));
        }
    }
}

// ---------------------------------------------------------------------------
// Layer 0 (scalar fp32; unchanged).
// ---------------------------------------------------------------------------
__global__ void __launch_bounds__(128)
layer0_kernel(const float* __restrict__ h_in, float* __restrict__ h_out,
              const float* __restrict__ bias, const float* __restrict__ gw,
              const float* __restrict__ gb) {
    constexpr int NP = 4;
    constexpr int TILE = 128 * NP;
    constexpr int HALO = K_N - 1;
    constexpr int HW = TILE + HALO;

    __shared__ __align__(16) float h_s[HW];
    __shared__ __align__(16) float w_s[K_N][C_N];
    __shared__ float gw_s[C_N][C_N];
    __shared__ float b_s[C_N];
    __shared__ float gb_s[C_N];

    const int b = blockIdx.y;
    const int tile0 = blockIdx.x * TILE;
    const int tid = threadIdx.x;

    for (int i = tid; i < K_N * C_N; i += 128) (&w_s[0][0])[i] = g_W0[i];
    for (int i = tid; i < C_N * C_N; i += 128) (&gw_s[0][0])[i] = gw[i];
    if (tid < C_N) { b_s[tid] = bias[tid]; gb_s[tid] = gb[tid]; }

    const float* hb = h_in + (size_t)b * T_LEN;
    for (int j = tid; j < HW; j += 128) {
        int t = tile0 - HALO + j;
        h_s[j] = (t >= 0) ? hb[t] : 0.0f;
    }
    __syncthreads();

    float acc[C_N][NP];
    #pragma unroll
    for (int o = 0; o < C_N; o++) {
        float bv = b_s[o];
        #pragma unroll
        for (int p = 0; p < NP; p++) acc[o][p] = bv;
    }

    #pragma unroll 1
    for (int k = 0; k < K_N; k++) {
        float hv[NP];
        #pragma unroll
        for (int p = 0; p < NP; p++) hv[p] = h_s[tid + k + p * 128];
        float wv[C_N];
        *(float4*)&wv[0] = *(const float4*)&w_s[k][0];
        *(float4*)&wv[4] = *(const float4*)&w_s[k][4];
        #pragma unroll
        for (int o = 0; o < C_N; o++)
            #pragma unroll
            for (int p = 0; p < NP; p++)
                acc[o][p] = fmaf(wv[o], hv[p], acc[o][p]);
    }

    float* ob = h_out + (size_t)b * C_N * T_LEN;
    u32 mx = 0;
    #pragma unroll
    for (int p = 0; p < NP; p++) {
        float prev = h_s[tid + HALO + p * 128];
        #pragma unroll
        for (int o = 0; o < C_N; o++) {
            float gate = gb_s[o];
            #pragma unroll
            for (int c = 0; c < C_N; c++) gate = fmaf(gw_s[o][c], acc[c][p], gate);
            float r = gated_act(acc[o][p], gate) + prev;
            mx = max(mx, __float_as_uint(fabsf(r)));
            ob[(size_t)o * T_LEN + tile0 + tid + p * 128] = r;
        }
    }
    mx = __reduce_max_sync(0xffffffffu, mx);
    if ((tid & 31) == 0) atomicMax(&g_hmax_bits[1], mx);
}

// ---------------------------------------------------------------------------
// Layers 1..17: int8 m16n8k32, 4-tap dense groups.
// Separate hi/lo tiles; each packs 2 time rows per 16B SMEM row, duplicated in
// 2 parity copies so any even-or-odd 4-row window is ldmatrix-addressable.
// Per group g (ages 4g..4g+3), per z: 2 LDSM + 3 MMA:
//   accA += Ahi*Bhi ; accB += Alo*Bhi ; accB += Ahi*Blo
// out = s*(16384*accA + 128*accB).
// ---------------------------------------------------------------------------
template <int DIL>
__global__ void __launch_bounds__(128, 7)
layer_mma(const float* __restrict__ h_in, float* __restrict__ h_out,
          const uint2* __restrict__ Bq,    // [13][2][32] uint2
          const float* __restrict__ bias, const float* __restrict__ gw,
          const float* __restrict__ gb, int li) {
    constexpr int R = TILE_M / DIL;
    constexpr int R16 = R / 16;
    constexpr int HALO = 52 * DIL;
    constexpr int TROWS = TILE_M + HALO;
    constexpr int CPROWS = (R + 52) / 2;   // 16B rows per parity copy per phase
    constexpr int CPB = CPROWS * 16;
    constexpr int PHB = 2 * CPB;           // bytes per phase per tile
    constexpr int TILE1 = DIL * PHB;       // one tile (hi or lo)
    constexpr int PARKPAD = 9;
    constexpr int PARKB = TILE_M * PARKPAD * 4;
    constexpr int R1 = ((((2 * TILE1) > PARKB) ? (2 * TILE1) : PARKB) + 15) & ~15;

    extern __shared__ __align__(16) char dyn[];
    char* tile = dyn;                      // hi tile [TILE1] then lo tile [TILE1]
    float* park = (float*)dyn;             // overlay after MMA
    float* f32res = (float*)(dyn + R1);    // fp32 residual [TILE_M][8]
    __shared__ float ctrl[80];             // bias[8], gb[8], gw[64]

    const int b = blockIdx.y;
    const int tile0 = blockIdx.x * TILE_M;
    const int tid = threadIdx.x;
    const int wid = tid >> 5;
    const int lane = tid & 31;

    if (tid < 8) ctrl[tid] = bias[tid];
    else if (tid < 16) ctrl[tid] = gb[tid - 8];
    else if (tid < 80) ctrl[tid] = gw[tid - 16];

    const float hmax = __uint_as_float(g_hmax_bits[li]);
    const float inv_s = 16256.0f / hmax;
    const float s_h = hmax / 16256.0f;
    const float s_w = g_wscale[li - 1];

    // Stage quantized hi/lo tiles (parity-duplicated), phase-major.
    const float* hb = h_in + (size_t)b * C_N * T_LEN;
    for (int j = tid; j < TROWS; j += 128) {
        int t = tile0 - HALO + j;
        float v[C_N];
        int Hh[8], Hl[8];
        #pragma unroll
        for (int c = 0; c < C_N; c++) {
            v[c] = (t >= 0) ? hb[(size_t)c * T_LEN + t] : 0.0f;
            int H = __float2int_rn(v[c] * inv_s);
            Hh[c] = (H + 64) >> 7;
            Hl[c] = H - (Hh[c] << 7);
        }
        u32 hi0 = pack4i(Hh[0], Hh[1], Hh[2], Hh[3]);
        u32 hi1 = pack4i(Hh[4], Hh[5], Hh[6], Hh[7]);
        u32 lo0 = pack4i(Hl[0], Hl[1], Hl[2], Hl[3]);
        u32 lo1 = pack4i(Hl[4], Hl[5], Hl[6], Hl[7]);
        int u = j / DIL;
        int p = j % DIL;
        char* phb = tile + p * PHB;
        int P = u & 1;
        // first half of copy P row u>>1 (= row u)
        *(uint2*)(phb + P * CPB + (u >> 1) * 16) = make_uint2(hi0, hi1);
        *(uint2*)(phb + TILE1 + P * CPB + (u >> 1) * 16) = make_uint2(lo0, lo1);
        // second half of the other-parity copy (row u again)
        int j2 = (u - 2 + P) >> 1;
        if (j2 >= 0) {
            int P2 = 1 - P;
            *(uint2*)(phb + P2 * CPB + j2 * 16 + 8) = make_uint2(hi0, hi1);
            *(uint2*)(phb + TILE1 + P2 * CPB + j2 * 16 + 8) = make_uint2(lo0, lo1);
        }
        int r = j - HALO;
        if (r >= 0) {
            *(float4*)&f32res[r * 8] = make_float4(v[0], v[1], v[2], v[3]);
            *(float4*)&f32res[r * 8 + 4] = make_float4(v[4], v[5], v[6], v[7]);
        }
    }
    __syncthreads();

    // Per-z ldmatrix base addresses (group 0; decrement 32B per group).
    const int mlane = lane & 15;
    const int kk = lane >> 4;
    u32 zb[4];
    #pragma unroll
    for (int z = 0; z < 4; z++) {
        int st = wid * 4 + z;
        int p = st / R16;
        int sub = st % R16;
        int m_out = sub * 16 + mlane;
        int P = (m_out + 1) & 1;           // parity of rb0 = m_out + 49
        int rb0 = m_out + 49;
        zb[z] = (u32)(p * PHB + P * CPB + ((rb0 - P) >> 1) * 16 + kk * 16);
    }

    const u32 t32 = smem_u32(tile);

    int accA[4][4], accB[4][4];
    #pragma unroll
    for (int z = 0; z < 4; z++)
        #pragma unroll
        for (int q = 0; q < 4; q++) { accA[z][q] = 0; accB[z][q] = 0; }

    {
        const uint2* bw = Bq + lane;
        #pragma unroll 4
        for (int g = 0; g < 13; g++) {
            uint2 bh = bw[g * 64];
            uint2 bl = bw[g * 64 + 32];
            const u32 off = (u32)(g * 32);
            #pragma unroll
            for (int z = 0; z < 4; z++) {
                u32 h0, h1, h2, h3, l0, l1, l2, l3;
                ldmA(h0, h1, h2, h3, t32 + zb[z] - off);
                ldmA(l0, l1, l2, l3, t32 + zb[z] + (u32)TILE1 - off);
                mma_s8(accA[z], h0, h1, h2, h3, bh.x, bh.y);
                mma_s8(accB[z], l0, l1, l2, l3, bh.x, bh.y);
                mma_s8(accB[z], h0, h1, h2, h3, bl.x, bl.y);
            }
        }
    }

    // Park combined fp32 conv outputs (overlay on tiles).
    const float c1 = s_h * s_w * 16384.0f;
    const float c2 = s_h * s_w * 128.0f;
    __syncthreads();
    {
        const int g = lane >> 2;
        const int tig = lane & 3;
        #pragma unroll
        for (int z = 0; z < 4; z++) {
            int st = wid * 4 + z;
            int p = st / R16;
            int sub = st % R16;
            int i0 = (sub * 16 + g) * DIL + p;
            int i1 = i0 + 8 * DIL;
            park[i0 * PARKPAD + 2 * tig]     = c1 * (float)accA[z][0] + c2 * (float)accB[z][0];
            park[i0 * PARKPAD + 2 * tig + 1] = c1 * (float)accA[z][1] + c2 * (float)accB[z][1];
            park[i1 * PARKPAD + 2 * tig]     = c1 * (float)accA[z][2] + c2 * (float)accB[z][2];
            park[i1 * PARKPAD + 2 * tig + 1] = c1 * (float)accA[z][3] + c2 * (float)accB[z][3];
        }
    }
    __syncthreads();

    // Epilogue: rows tid and tid+128; residual from SMEM; track out max.
    float* ob = h_out + (size_t)b * C_N * T_LEN;
    u32 mx = 0;
    #pragma unroll
    for (int half = 0; half < 2; half++) {
        const int r = tid + half * 128;
        float outv[C_N];
        #pragma unroll
        for (int o = 0; o < C_N; o++) outv[o] = park[r * PARKPAD + o] + ctrl[o];
        float4 p0 = *(const float4*)&f32res[r * 8];
        float4 p1 = *(const float4*)&f32res[r * 8 + 4];
        float prev[C_N] = {p0.x, p0.y, p0.z, p0.w, p1.x, p1.y, p1.z, p1.w};
        #pragma unroll
        for (int o = 0; o < C_N; o++) {
            float gate = ctrl[8 + o];
            #pragma unroll
            for (int c = 0; c < C_N; c++)
                gate = fmaf(ctrl[16 + o * 8 + c], outv[c], gate);
            float rr = gated_act(outv[o], gate) + prev[o];
            mx = max(mx, __float_as_uint(fabsf(rr)));
            ob[(size_t)o * T_LEN + tile0 + r] = rr;
        }
    }
    mx = __reduce_max_sync(0xffffffffu, mx);
    if (lane == 0) atomicMax(&g_hmax_bits[li + 1], mx);
}

// ---------------------------------------------------------------------------
// Head (unchanged)
// ---------------------------------------------------------------------------
__global__ void __launch_bounds__(256)
head_kernel(const float* __restrict__ h,
            const float* __restrict__ mean_w, const float* __restrict__ mean_b,
            const float* __restrict__ lv_w, const float* __restrict__ lv_b,
            float* __restrict__ out) {
    const int b = blockIdx.y;
    const int t0 = (blockIdx.x * 256 + threadIdx.x) * 4;
    if (t0 >= T_LEN) return;
    const float* hbp = h + (size_t)b * C_N * T_LEN;
    float m[4], lv[4];
    float mb = mean_b[0], lb = lv_b[0];
    #pragma unroll
    for (int p = 0; p < 4; p++) { m[p] = mb; lv[p] = lb; }
    #pragma unroll
    for (int c = 0; c < C_N; c++) {
        float4 hv = *(const float4*)&hbp[(size_t)c * T_LEN + t0];
        float mw = mean_w[c], lw = lv_w[c];
        m[0] = fmaf(mw, hv.x, m[0]); lv[0] = fmaf(lw, hv.x, lv[0]);
        m[1] = fmaf(mw, hv.y, m[1]); lv[1] = fmaf(lw, hv.y, lv[1]);
        m[2] = fmaf(mw, hv.z, m[2]); lv[2] = fmaf(lw, hv.z, lv[2]);
        m[3] = fmaf(mw, hv.w, m[3]); lv[3] = fmaf(lw, hv.w, lv[3]);
    }
    float s[4];
    #pragma unroll
    for (int p = 0; p < 4; p++) s[p] = expf(0.5f * lv[p]);
    *(float4*)&out[(size_t)b * T_LEN + t0] = make_float4(m[0], m[1], m[2], m[3]);
    *(float4*)&out[(size_t)B_N * T_LEN + (size_t)b * T_LEN + t0] =
        make_float4(s[0], s[1], s[2], s[3]);
}

// ---------------------------------------------------------------------------
static int smem_for_dil(int d) {
    int tile1 = (TILE_M + 52 * d) * 16;    // one tile (hi or lo)
    int parkb = TILE_M * 9 * 4;
    int r1 = (2 * tile1 > parkb) ? 2 * tile1 : parkb;
    r1 = (r1 + 15) & ~15;
    return r1 + TILE_M * 8 * 4;            // + fp32 residual buffer
}

extern "C" void kernel_launch(void* const* d_in, const int* in_sizes, int n_in,
                              void* d_out, int out_size) {
    (void)in_sizes; (void)n_in; (void)out_size;
    const float* x      = (const float*)d_in[0];
    const float* v0     = (const float*)d_in[1];
    const float* g0     = (const float*)d_in[2];
    const float* b0     = (const float*)d_in[3];
    const float* gw0    = (const float*)d_in[4];
    const float* gb0    = (const float*)d_in[5];
    const float* vs     = (const float*)d_in[6];
    const float* gs     = (const float*)d_in[7];
    const float* bs     = (const float*)d_in[8];
    const float* gws    = (const float*)d_in[9];
    const float* gbs    = (const float*)d_in[10];
    const float* mean_w = (const float*)d_in[11];
    const float* mean_b = (const float*)d_in[12];
    const float* lv_w   = (const float*)d_in[13];
    const float* lv_b   = (const float*)d_in[14];

    float *bufA, *bufB;
    uint2* Bq;
    cudaGetSymbolAddress((void**)&bufA, g_h0);
    cudaGetSymbolAddress((void**)&bufB, g_h1);
    cudaGetSymbolAddress((void**)&Bq, g_Bq);

    cudaFuncSetAttribute(layer_mma<1>, cudaFuncAttributeMaxDynamicSharedMemorySize, smem_for_dil(1));
    cudaFuncSetAttribute(layer_mma<2>, cudaFuncAttributeMaxDynamicSharedMemorySize, smem_for_dil(2));
    cudaFuncSetAttribute(layer_mma<4>, cudaFuncAttributeMaxDynamicSharedMemorySize, smem_for_dil(4));
    cudaFuncSetAttribute(layer_mma<8>, cudaFuncAttributeMaxDynamicSharedMemorySize, smem_for_dil(8));

    prep_weights<<<18, 256>>>(v0, g0, vs, gs);

    layer0_kernel<<<dim3(T_LEN / 512, B_N), 128>>>(x, bufA, b0, gw0, gb0);

    static const int dils[18] = {1,1,1,1,1,1,1,2,2,2,2,4,4,4,4,8,8,8};
    dim3 grid(T_LEN / TILE_M, B_N);
    float* cur = bufA;
    float* nxt = bufB;
    for (int i = 1; i < 18; i++) {
        const uint2* Wl  = Bq + (size_t)(i - 1) * 832;
        const float* bl  = bs  + (i - 1) * C_N;
        const float* gwl = gws + (i - 1) * C_N * C_N;
        const float* gbl = gbs + (i - 1) * C_N;
        switch (dils[i]) {
            case 1: layer_mma<1><<<grid, 128, smem_for_dil(1)>>>(cur, nxt, Wl, bl, gwl, gbl, i); break;
            case 2: layer_mma<2><<<grid, 128, smem_for_dil(2)>>>(cur, nxt, Wl, bl, gwl, gbl, i); break;
            case 4: layer_mma<4><<<grid, 128, smem_for_dil(4)>>>(cur, nxt, Wl, bl, gwl, gbl, i); break;
            case 8: layer_mma<8><<<grid, 128, smem_for_dil(8)>>>(cur, nxt, Wl, bl, gwl, gbl, i); break;
        }
        float* t = cur; cur = nxt; nxt = t;
    }

    head_kernel<<<dim3(T_LEN / (256 * 4), B_N), 256>>>(
        cur, mean_w, mean_b, lv_w, lv_b, (float*)d_out);
}

// round 17
// speedup vs baseline: 1.4298x; 1.4298x over previous
#include <cuda_runtime.h>
#include <cuda_bf16.h>
#include <math.h>
#include <stdint.h>

typedef uint32_t u32;
typedef uint64_t u64;

#define T_LEN 262144
#define B_N 8
#define C_N 8
#define K_N 50
#define TILE_M 256

// Ping-pong hidden state [B][C][T]
__device__ float g_h0[B_N * C_N * T_LEN];
__device__ float g_h1[B_N * C_N * T_LEN];
// Layer-0 scalar weights [k][o]
__device__ float g_W0[K_N * C_N];
// Layers 1..17 int8 B fragments (compressed): [layer][q(25)][lane(32)] uint2
__device__ uint2 g_Bq[17 * 25 * 32];
__device__ float g_wscale[17];
// |h| max bit-patterns; g_hmax_bits[i] = max |input of mma-layer i|
__device__ unsigned int g_hmax_bits[19];

// ---------------------------------------------------------------------------
__device__ __forceinline__ u32 smem_u32(const void* p) {
    return (u32)__cvta_generic_to_shared(p);
}
__device__ __forceinline__ void ldmA(u32& a0, u32& a1, u32& a2, u32& a3, u32 addr) {
    asm volatile("ldmatrix.sync.aligned.m8n8.x4.shared.b16 {%0,%1,%2,%3}, [%4];"
                 : "=r"(a0), "=r"(a1), "=r"(a2), "=r"(a3) : "r"(addr));
}
__device__ __forceinline__ void mma_s8(int* c, u32 a0, u32 a1, u32 a2, u32 a3,
                                       u32 b0, u32 b1) {
    asm volatile("mma.sync.aligned.m16n8k32.row.col.s32.s8.s8.s32 "
                 "{%0,%1,%2,%3},{%4,%5,%6,%7},{%8,%9},{%0,%1,%2,%3};"
                 : "+r"(c[0]), "+r"(c[1]), "+r"(c[2]), "+r"(c[3])
                 : "r"(a0), "r"(a1), "r"(a2), "r"(a3), "r"(b0), "r"(b1));
}
__device__ __forceinline__ u32 pack4i(int a, int b, int c, int d) {
    return (u32)(a & 0xff) | ((u32)(b & 0xff) << 8) |
           ((u32)(c & 0xff) << 16) | ((u32)(d & 0xff) << 24);
}
// tanh(x)*sigmoid(g) with ONE fast division.
__device__ __forceinline__ float gated_act(float x, float g) {
    x = fminf(fmaxf(x, -20.0f), 20.0f);
    g = fminf(fmaxf(g, -20.0f), 20.0f);
    float e = __expf(-2.0f * x);
    float f = __expf(-g);
    return __fdividef(1.0f - e, (1.0f + e) * (1.0f + f));
}

// ---------------------------------------------------------------------------
// Weight prep (identical to round 14).
// ---------------------------------------------------------------------------
__global__ void prep_weights(const float* __restrict__ v0,
                             const float* __restrict__ g0,
                             const float* __restrict__ vs,
                             const float* __restrict__ gs) {
    int l = blockIdx.x;
    int tid = threadIdx.x;

    if (l == 0) {
        if (tid < C_N) {
            int o = tid;
            float s = 0.0f;
            for (int k = 0; k < K_N; k++) {
                float x = v0[o * K_N + k];
                s += x * x;
            }
            float scale = g0[o] * rsqrtf(s);
            for (int k = 0; k < K_N; k++)
                g_W0[k * C_N + o] = scale * v0[o * K_N + k];
        }
        return;
    }

    __shared__ float osc[C_N];
    __shared__ float w_s[C_N * C_N * K_N];
    __shared__ float wred[8];
    __shared__ float swmax;

    const float* v = vs + (size_t)(l - 1) * C_N * C_N * K_N;
    int o = tid >> 5;
    int lane = tid & 31;

    {
        float s = 0.0f;
        for (int i = lane; i < C_N * K_N; i += 32) {
            float x = v[o * C_N * K_N + i];
            s += x * x;
        }
        #pragma unroll
        for (int off = 16; off > 0; off >>= 1)
            s += __shfl_down_sync(0xffffffffu, s, off);
        if (lane == 0) osc[o] = gs[(l - 1) * C_N + o] * rsqrtf(s);
    }
    __syncthreads();

    float m = 0.0f;
    for (int i = tid; i < 3200; i += 256) {
        float w = v[i] * osc[i / (C_N * K_N)];
        w_s[i] = w;
        m = fmaxf(m, fabsf(w));
    }
    #pragma unroll
    for (int off = 16; off > 0; off >>= 1)
        m = fmaxf(m, __shfl_down_sync(0xffffffffu, m, off));
    if (lane == 0) wred[o] = m;
    __syncthreads();
    if (tid == 0) {
        float wm = wred[0];
        #pragma unroll
        for (int i = 1; i < 8; i++) wm = fmaxf(wm, wred[i]);
        swmax = wm;
        g_wscale[l - 1] = wm / 16256.0f;
    }
    __syncthreads();

    if (tid < 32) {
        int oo = tid >> 2;
        int T = tid & 3;
        float inv = 16256.0f / swmax;
        for (int q = 0; q < 25; q++) {
            int k1 = 48 - 2 * q;
            int k2 = 49 - 2 * q;
            int ha[8], la[8], hb[8], lb[8];
            #pragma unroll
            for (int c = 0; c < 8; c++) {
                int W = __float2int_rn(w_s[oo * 400 + c * 50 + k1] * inv);
                ha[c] = (W + 64) >> 7;
                la[c] = W - (ha[c] << 7);
                W = __float2int_rn(w_s[oo * 400 + c * 50 + k2] * inv);
                hb[c] = (W + 64) >> 7;
                lb[c] = W - (hb[c] << 7);
            }
            u32 b0_2, b1_2;
            if (T < 2) {
                int c0 = 4 * T;
                b0_2 = pack4i(la[c0], la[c0+1], la[c0+2], la[c0+3]);
                b1_2 = pack4i(lb[c0], lb[c0+1], lb[c0+2], lb[c0+3]);
            } else {
                int c0 = 4 * (T - 2);
                b0_2 = pack4i(ha[c0], ha[c0+1], ha[c0+2], ha[c0+3]);
                b1_2 = pack4i(hb[c0], hb[c0+1], hb[c0+2], hb[c0+3]);
            }
            g_Bq[(size_t)(l - 1) * 800 + q * 32 + tid] = make_uint2(b0_2, b1_2);
        }
    }
}

// ---------------------------------------------------------------------------
// Layer 0 (scalar fp32; identical to round 14).
// ---------------------------------------------------------------------------
__global__ void __launch_bounds__(128)
layer0_kernel(const float* __restrict__ h_in, float* __restrict__ h_out,
              const float* __restrict__ bias, const float* __restrict__ gw,
              const float* __restrict__ gb) {
    constexpr int NP = 4;
    constexpr int TILE = 128 * NP;
    constexpr int HALO = K_N - 1;
    constexpr int HW = TILE + HALO;

    __shared__ __align__(16) float h_s[HW];
    __shared__ __align__(16) float w_s[K_N][C_N];
    __shared__ float gw_s[C_N][C_N];
    __shared__ float b_s[C_N];
    __shared__ float gb_s[C_N];

    const int b = blockIdx.y;
    const int tile0 = blockIdx.x * TILE;
    const int tid = threadIdx.x;

    for (int i = tid; i < K_N * C_N; i += 128) (&w_s[0][0])[i] = g_W0[i];
    for (int i = tid; i < C_N * C_N; i += 128) (&gw_s[0][0])[i] = gw[i];
    if (tid < C_N) { b_s[tid] = bias[tid]; gb_s[tid] = gb[tid]; }

    const float* hb = h_in + (size_t)b * T_LEN;
    for (int j = tid; j < HW; j += 128) {
        int t = tile0 - HALO + j;
        h_s[j] = (t >= 0) ? hb[t] : 0.0f;
    }
    __syncthreads();

    float acc[C_N][NP];
    #pragma unroll
    for (int o = 0; o < C_N; o++) {
        float bv = b_s[o];
        #pragma unroll
        for (int p = 0; p < NP; p++) acc[o][p] = bv;
    }

    #pragma unroll 1
    for (int k = 0; k < K_N; k++) {
        float hv[NP];
        #pragma unroll
        for (int p = 0; p < NP; p++) hv[p] = h_s[tid + k + p * 128];
        float wv[C_N];
        *(float4*)&wv[0] = *(const float4*)&w_s[k][0];
        *(float4*)&wv[4] = *(const float4*)&w_s[k][4];
        #pragma unroll
        for (int o = 0; o < C_N; o++)
            #pragma unroll
            for (int p = 0; p < NP; p++)
                acc[o][p] = fmaf(wv[o], hv[p], acc[o][p]);
    }

    float* ob = h_out + (size_t)b * C_N * T_LEN;
    u32 mx = 0;
    #pragma unroll
    for (int p = 0; p < NP; p++) {
        float prev = h_s[tid + HALO + p * 128];
        #pragma unroll
        for (int o = 0; o < C_N; o++) {
            float gate = gb_s[o];
            #pragma unroll
            for (int c = 0; c < C_N; c++) gate = fmaf(gw_s[o][c], acc[c][p], gate);
            float r = gated_act(acc[o][p], gate) + prev;
            mx = max(mx, __float_as_uint(fabsf(r)));
            ob[(size_t)o * T_LEN + tile0 + tid + p * 128] = r;
        }
    }
    mx = __reduce_max_sync(0xffffffffu, mx);
    if ((tid & 31) == 0) atomicMax(&g_hmax_bits[1], mx);
}

// ---------------------------------------------------------------------------
// Layers 1..17 (round-14 layout).  LAST=1: fuse head — epilogue computes
// means/stds directly into d_out (no h write, no hmax, no head kernel).
// ---------------------------------------------------------------------------
template <int DIL, int LAST>
__global__ void __launch_bounds__(128, 7)
layer_mma(const float* __restrict__ h_in, float* __restrict__ h_out,
          const uint2* __restrict__ Bq,    // [25][32] uint2
          const float* __restrict__ bias, const float* __restrict__ gw,
          const float* __restrict__ gb, int li,
          const float* __restrict__ mw, const float* __restrict__ mb2,
          const float* __restrict__ lw, const float* __restrict__ lb2) {
    constexpr int R = TILE_M / DIL;
    constexpr int R16 = R / 16;
    constexpr int PHROWS = R + 49;
    constexpr int TROWS = TILE_M + 49 * DIL;
    constexpr int PARKPAD = 9;
    constexpr int TILEB = TROWS * 16;
    constexpr int PARKB = TILE_M * PARKPAD * 4;
    constexpr int R1 = (((TILEB > PARKB) ? TILEB : PARKB) + 15) & ~15;

    extern __shared__ __align__(16) char dyn[];
    char* tile = dyn;                      // int8 tile [TROWS][16]
    float* park = (float*)dyn;             // overlay after MMA
    float* f32res = (float*)(dyn + R1);    // fp32 residual [TILE_M][8]
    __shared__ float ctrl[98];             // bias, gb, gw, [80..95] mw/lw, [96,97] mb/lb

    const int b = blockIdx.y;
    const int tile0 = blockIdx.x * TILE_M;
    const int tid = threadIdx.x;
    const int wid = tid >> 5;
    const int lane = tid & 31;

    if (tid < 8) ctrl[tid] = bias[tid];
    else if (tid < 16) ctrl[tid] = gb[tid - 8];
    else if (tid < 80) ctrl[tid] = gw[tid - 16];
    if (LAST) {
        if (tid >= 80 && tid < 88) ctrl[tid] = mw[tid - 80];
        else if (tid >= 88 && tid < 96) ctrl[tid] = lw[tid - 88];
        else if (tid == 96) ctrl[96] = mb2[0];
        else if (tid == 97) ctrl[97] = lb2[0];
    }

    const float hmax = __uint_as_float(g_hmax_bits[li]);
    const float inv_s = 16256.0f / hmax;
    const float s_h = hmax / 16256.0f;
    const float s_w = g_wscale[li - 1];

    // Stage quantized tile, phase-major; one thread per time row (STS.128).
    const float* hb = h_in + (size_t)b * C_N * T_LEN;
    for (int j = tid; j < TROWS; j += 128) {
        int t = tile0 - 49 * DIL + j;
        float v[C_N];
        int Hh[8], Hl[8];
        #pragma unroll
        for (int c = 0; c < C_N; c++) {
            v[c] = (t >= 0) ? hb[(size_t)c * T_LEN + t] : 0.0f;
            int H = __float2int_rn(v[c] * inv_s);
            Hh[c] = (H + 64) >> 7;
            Hl[c] = H - (Hh[c] << 7);
        }
        int row = j / DIL;
        int p = j % DIL;
        uint4 w;
        w.x = pack4i(Hh[0], Hh[1], Hh[2], Hh[3]);
        w.y = pack4i(Hh[4], Hh[5], Hh[6], Hh[7]);
        w.z = pack4i(Hl[0], Hl[1], Hl[2], Hl[3]);
        w.w = pack4i(Hl[4], Hl[5], Hl[6], Hl[7]);
        *(uint4*)&tile[(p * PHROWS + row) * 16] = w;
        int r = j - 49 * DIL;
        if (r >= 0) {
            *(float4*)&f32res[r * 8] = make_float4(v[0], v[1], v[2], v[3]);
            *(float4*)&f32res[r * 8 + 4] = make_float4(v[4], v[5], v[6], v[7]);
        }
    }
    __syncthreads();

    // Per-z ldmatrix base offsets (16B rows).
    const int rowlane = (lane & 15) + (lane >> 4);
    u32 zb[4];
    #pragma unroll
    for (int z = 0; z < 4; z++) {
        int st = wid * 4 + z;
        int p = st / R16;
        int sub = st % R16;
        zb[z] = (u32)((p * PHROWS + sub * 16 + 48 + rowlane) * 16);
    }

    const u32 t32 = smem_u32(tile);
    const bool hiLane = (lane & 3) < 2;

    int acc1[4][4], acc2[4][4];
    #pragma unroll
    for (int z = 0; z < 4; z++)
        #pragma unroll
        for (int q = 0; q < 4; q++) { acc1[z][q] = 0; acc2[z][q] = 0; }

    {
        const uint2* bw = Bq + lane;
        uint2 bb = *bw;                      // prefetch q=0
        #pragma unroll 5
        for (int q = 0; q < 25; q++) {
            uint2 nb = (q < 24) ? bw[(q + 1) * 32] : bb;
            u32 m1x = __shfl_sync(0xffffffffu, bb.x, (lane + 2) & 31);
            u32 m1y = __shfl_sync(0xffffffffu, bb.y, (lane + 2) & 31);
            m1x = hiLane ? m1x : 0u;
            m1y = hiLane ? m1y : 0u;
            u32 off = (u32)(q * 32);
            #pragma unroll
            for (int z = 0; z < 4; z++) {
                u32 a0, a1, a2, a3;
                ldmA(a0, a1, a2, a3, t32 + zb[z] - off);
                mma_s8(acc1[z], a0, a1, a2, a3, m1x, m1y);
                mma_s8(acc2[z], a0, a1, a2, a3, bb.x, bb.y);
            }
            bb = nb;
        }
    }

    // Park combined fp32 conv outputs (overlay on tile).
    const float c1 = s_h * s_w * 16384.0f;
    const float c2 = s_h * s_w * 128.0f;
    __syncthreads();
    {
        const int g = lane >> 2;
        const int tig = lane & 3;
        #pragma unroll
        for (int z = 0; z < 4; z++) {
            int st = wid * 4 + z;
            int p = st / R16;
            int sub = st % R16;
            int i0 = (sub * 16 + g) * DIL + p;
            int i1 = i0 + 8 * DIL;
            park[i0 * PARKPAD + 2 * tig]     = c1 * (float)acc1[z][0] + c2 * (float)acc2[z][0];
            park[i0 * PARKPAD + 2 * tig + 1] = c1 * (float)acc1[z][1] + c2 * (float)acc2[z][1];
            park[i1 * PARKPAD + 2 * tig]     = c1 * (float)acc1[z][2] + c2 * (float)acc2[z][2];
            park[i1 * PARKPAD + 2 * tig + 1] = c1 * (float)acc1[z][3] + c2 * (float)acc2[z][3];
        }
    }
    __syncthreads();

    // Epilogue: rows tid and tid+128; residual from SMEM.
    u32 mx = 0;
    #pragma unroll
    for (int half = 0; half < 2; half++) {
        const int r = tid + half * 128;
        float outv[C_N];
        #pragma unroll
        for (int o = 0; o < C_N; o++) outv[o] = park[r * PARKPAD + o] + ctrl[o];
        float4 p0 = *(const float4*)&f32res[r * 8];
        float4 p1 = *(const float4*)&f32res[r * 8 + 4];
        float prev[C_N] = {p0.x, p0.y, p0.z, p0.w, p1.x, p1.y, p1.z, p1.w};
        if (LAST) {
            float m = ctrl[96];
            float lv = ctrl[97];
            #pragma unroll
            for (int o = 0; o < C_N; o++) {
                float gate = ctrl[8 + o];
                #pragma unroll
                for (int c = 0; c < C_N; c++)
                    gate = fmaf(ctrl[16 + o * 8 + c], outv[c], gate);
                float rr = gated_act(outv[o], gate) + prev[o];
                m = fmaf(ctrl[80 + o], rr, m);
                lv = fmaf(ctrl[88 + o], rr, lv);
            }
            h_out[(size_t)b * T_LEN + tile0 + r] = m;
            h_out[(size_t)B_N * T_LEN + (size_t)b * T_LEN + tile0 + r] =
                expf(0.5f * lv);
        } else {
            float* ob = h_out + (size_t)b * C_N * T_LEN;
            #pragma unroll
            for (int o = 0; o < C_N; o++) {
                float gate = ctrl[8 + o];
                #pragma unroll
                for (int c = 0; c < C_N; c++)
                    gate = fmaf(ctrl[16 + o * 8 + c], outv[c], gate);
                float rr = gated_act(outv[o], gate) + prev[o];
                mx = max(mx, __float_as_uint(fabsf(rr)));
                ob[(size_t)o * T_LEN + tile0 + r] = rr;
            }
        }
    }
    if (!LAST) {
        mx = __reduce_max_sync(0xffffffffu, mx);
        if (lane == 0) atomicMax(&g_hmax_bits[li + 1], mx);
    }
}

// ---------------------------------------------------------------------------
static int smem_for_dil(int d) {
    int tileb = (TILE_M + 49 * d) * 16;
    int parkb = TILE_M * 9 * 4;
    int r1 = (tileb > parkb ? tileb : parkb);
    r1 = (r1 + 15) & ~15;
    return r1 + TILE_M * 8 * 4;
}

extern "C" void kernel_launch(void* const* d_in, const int* in_sizes, int n_in,
                              void* d_out, int out_size) {
    (void)in_sizes; (void)n_in; (void)out_size;
    const float* x      = (const float*)d_in[0];
    const float* v0     = (const float*)d_in[1];
    const float* g0     = (const float*)d_in[2];
    const float* b0     = (const float*)d_in[3];
    const float* gw0    = (const float*)d_in[4];
    const float* gb0    = (const float*)d_in[5];
    const float* vs     = (const float*)d_in[6];
    const float* gs     = (const float*)d_in[7];
    const float* bs     = (const float*)d_in[8];
    const float* gws    = (const float*)d_in[9];
    const float* gbs    = (const float*)d_in[10];
    const float* mean_w = (const float*)d_in[11];
    const float* mean_b = (const float*)d_in[12];
    const float* lv_w   = (const float*)d_in[13];
    const float* lv_b   = (const float*)d_in[14];

    float *bufA, *bufB;
    uint2* Bq;
    cudaGetSymbolAddress((void**)&bufA, g_h0);
    cudaGetSymbolAddress((void**)&bufB, g_h1);
    cudaGetSymbolAddress((void**)&Bq, g_Bq);

    cudaFuncSetAttribute(layer_mma<1, 0>, cudaFuncAttributeMaxDynamicSharedMemorySize, smem_for_dil(1));
    cudaFuncSetAttribute(layer_mma<2, 0>, cudaFuncAttributeMaxDynamicSharedMemorySize, smem_for_dil(2));
    cudaFuncSetAttribute(layer_mma<4, 0>, cudaFuncAttributeMaxDynamicSharedMemorySize, smem_for_dil(4));
    cudaFuncSetAttribute(layer_mma<8, 0>, cudaFuncAttributeMaxDynamicSharedMemorySize, smem_for_dil(8));
    cudaFuncSetAttribute(layer_mma<8, 1>, cudaFuncAttributeMaxDynamicSharedMemorySize, smem_for_dil(8));

    prep_weights<<<18, 256>>>(v0, g0, vs, gs);

    layer0_kernel<<<dim3(T_LEN / 512, B_N), 128>>>(x, bufA, b0, gw0, gb0);

    static const int dils[18] = {1,1,1,1,1,1,1,2,2,2,2,4,4,4,4,8,8,8};
    dim3 grid(T_LEN / TILE_M, B_N);
    float* cur = bufA;
    float* nxt = bufB;
    for (int i = 1; i < 18; i++) {
        const uint2* Wl  = Bq + (size_t)(i - 1) * 800;
        const float* bl  = bs  + (i - 1) * C_N;
        const float* gwl = gws + (i - 1) * C_N * C_N;
        const float* gbl = gbs + (i - 1) * C_N;
        if (i == 17) {
            layer_mma<8, 1><<<grid, 128, smem_for_dil(8)>>>(
                cur, (float*)d_out, Wl, bl, gwl, gbl, i,
                mean_w, mean_b, lv_w, lv_b);
            break;
        }
        switch (dils[i]) {
            case 1: layer_mma<1, 0><<<grid, 128, smem_for_dil(1)>>>(cur, nxt, Wl, bl, gwl, gbl, i, mean_w, mean_b, lv_w, lv_b); break;
            case 2: layer_mma<2, 0><<<grid, 128, smem_for_dil(2)>>>(cur, nxt, Wl, bl, gwl, gbl, i, mean_w, mean_b, lv_w, lv_b); break;
            case 4: layer_mma<4, 0><<<grid, 128, smem_for_dil(4)>>>(cur, nxt, Wl, bl, gwl, gbl, i, mean_w, mean_b, lv_w, lv_b); break;
            case 8: layer_mma<8, 0><<<grid, 128, smem_for_dil(8)>>>(cur, nxt, Wl, bl, gwl, gbl, i, mean_w, mean_b, lv_w, lv_b); break;
        }
        float* t = cur; cur = nxt; nxt = t;
    }
}